// round 1
// baseline (speedup 1.0000x reference)
#include <cuda_runtime.h>
#include <math.h>

#define T_DIM 4096
#define D_DIM 1024
#define H_NUM 16
#define C_DIM 64
#define FPAD 68   // 64 + 4 pad: row stride in floats for flash smem tiles

// Scratch (allocations are forbidden; use device globals)
__device__ float g_qkv[T_DIM * 3 * D_DIM];   // 48 MB: [T][3*D]
__device__ float g_att[T_DIM * D_DIM];       // 16 MB: [T][D]

// ---------------------------------------------------------------------------
// SGEMM, C[M,N] = A[M,K] * B[N,K]^T  (both row-major, NT)
// 128x128 block tile, BK=8, 256 threads, 8x8 register fragments.
// Requires M%128==0, N%128==0, K%8==0 (true for all our shapes).
// ---------------------------------------------------------------------------
__global__ void sgemm_nt(const float* __restrict__ A, const float* __restrict__ B,
                         float* __restrict__ C, int M, int N, int K) {
    __shared__ float As[8][128];
    __shared__ float Bs[8][128];

    const int tid = threadIdx.x;
    const int bm  = blockIdx.y * 128;
    const int bn  = blockIdx.x * 128;
    const int tx  = tid & 15;     // 0..15
    const int ty  = tid >> 4;     // 0..15
    const int lr  = tid >> 1;     // 0..127 load row
    const int lk  = (tid & 1) * 4;

    const float* Ap = A + (size_t)(bm + lr) * K + lk;
    const float* Bp = B + (size_t)(bn + lr) * K + lk;

    float acc[8][8];
#pragma unroll
    for (int i = 0; i < 8; i++)
#pragma unroll
        for (int j = 0; j < 8; j++) acc[i][j] = 0.f;

    for (int k0 = 0; k0 < K; k0 += 8) {
        float4 a4 = *(const float4*)(Ap + k0);
        float4 b4 = *(const float4*)(Bp + k0);
        As[lk + 0][lr] = a4.x; As[lk + 1][lr] = a4.y;
        As[lk + 2][lr] = a4.z; As[lk + 3][lr] = a4.w;
        Bs[lk + 0][lr] = b4.x; Bs[lk + 1][lr] = b4.y;
        Bs[lk + 2][lr] = b4.z; Bs[lk + 3][lr] = b4.w;
        __syncthreads();

#pragma unroll
        for (int k = 0; k < 8; k++) {
            float a[8], b[8];
            *(float4*)&a[0] = *(const float4*)&As[k][ty * 4];
            *(float4*)&a[4] = *(const float4*)&As[k][64 + ty * 4];
            *(float4*)&b[0] = *(const float4*)&Bs[k][tx * 4];
            *(float4*)&b[4] = *(const float4*)&Bs[k][64 + tx * 4];
#pragma unroll
            for (int i = 0; i < 8; i++)
#pragma unroll
                for (int j = 0; j < 8; j++) acc[i][j] += a[i] * b[j];
        }
        __syncthreads();
    }

#pragma unroll
    for (int i = 0; i < 8; i++) {
        int row = bm + ((i < 4) ? (ty * 4 + i) : (64 + ty * 4 + (i - 4)));
        float4 v0 = make_float4(acc[i][0], acc[i][1], acc[i][2], acc[i][3]);
        float4 v1 = make_float4(acc[i][4], acc[i][5], acc[i][6], acc[i][7]);
        *(float4*)&C[(size_t)row * N + bn + tx * 4]      = v0;
        *(float4*)&C[(size_t)row * N + bn + 64 + tx * 4] = v1;
    }
}

// ---------------------------------------------------------------------------
// RoPE applied in place to q and k inside g_qkv [T][3*D].
// One thread per (t, h, pair p in 0..31); handles q and k.
// ---------------------------------------------------------------------------
__global__ void rope_kernel(float* __restrict__ qkv) {
    int idx = blockIdx.x * blockDim.x + threadIdx.x;
    if (idx >= T_DIM * H_NUM * (C_DIM / 2)) return;
    int t = idx >> 9;           // / (16*32)
    int r = idx & 511;
    int h = r >> 5;
    int p = r & 31;

    // inv_freq = 10000^{-p/32}
    float inv_freq = expf(-(float)p * (logf(10000.0f) / 32.0f));
    float ang = (float)t * inv_freq;
    float s, c;
    sincosf(ang, &s, &c);

    size_t base_q = (size_t)t * (3 * D_DIM) + h * C_DIM + 2 * p;
    size_t base_k = base_q + D_DIM;

    float x1 = qkv[base_q], x2 = qkv[base_q + 1];
    qkv[base_q]     = x1 * c - x2 * s;
    qkv[base_q + 1] = x2 * c + x1 * s;

    float y1 = qkv[base_k], y2 = qkv[base_k + 1];
    qkv[base_k]     = y1 * c - y2 * s;
    qkv[base_k + 1] = y2 * c + y1 * s;
}

// ---------------------------------------------------------------------------
// Flash attention, fp32, causal. Bq=Bk=64, C=64, 256 threads.
// Fragment mapping: thread (tx=tid%16, ty=tid/16) owns rows {ty+16i},
// cols {tx+16j}, i,j in 0..3. This striding keeps all smem accesses
// conflict-free with FPAD=68. Row-wise softmax reductions are half-warp
// shfl (lanes sharing ty).
// ---------------------------------------------------------------------------
__global__ void flash_attn(const float* __restrict__ qkv, float* __restrict__ out) {
    extern __shared__ float sm[];
    float* Qs = sm;
    float* Ks = sm + 64 * FPAD;
    float* Vs = sm + 2 * 64 * FPAD;
    float* Ps = sm + 3 * 64 * FPAD;

    const int h   = blockIdx.y;
    const int qb  = gridDim.x - 1 - blockIdx.x;   // reverse order: big blocks first
    const int q0  = qb * 64;
    const int tid = threadIdx.x;
    const int tx  = tid & 15;
    const int ty  = tid >> 4;
    const int hcol = h * C_DIM;

    // Load Q tile [64][64]
    {
        int r  = tid >> 4;
        int c4 = (tid & 15) * 4;
#pragma unroll
        for (int rr = 0; rr < 64; rr += 16)
            *(float4*)&Qs[(r + rr) * FPAD + c4] =
                *(const float4*)&qkv[(size_t)(q0 + r + rr) * (3 * D_DIM) + hcol + c4];
    }

    float m_i[4], l_i[4], o[4][4];
#pragma unroll
    for (int i = 0; i < 4; i++) {
        m_i[i] = -1e30f; l_i[i] = 0.f;
#pragma unroll
        for (int j = 0; j < 4; j++) o[i][j] = 0.f;
    }

    for (int kb = 0; kb <= qb; kb++) {
        const int k0 = kb * 64;
        __syncthreads();  // prior iter's PV reads of Ks/Vs/Ps done; Q loads visible

        // Load K, V tiles
        {
            int r  = tid >> 4;
            int c4 = (tid & 15) * 4;
#pragma unroll
            for (int rr = 0; rr < 64; rr += 16) {
                const float* src = &qkv[(size_t)(k0 + r + rr) * (3 * D_DIM) + hcol + c4];
                *(float4*)&Ks[(r + rr) * FPAD + c4] = *(const float4*)(src + D_DIM);
                *(float4*)&Vs[(r + rr) * FPAD + c4] = *(const float4*)(src + 2 * D_DIM);
            }
        }
        __syncthreads();

        // S = Q K^T (64x64x64), 4x4 frag per thread
        float s[4][4];
#pragma unroll
        for (int i = 0; i < 4; i++)
#pragma unroll
            for (int j = 0; j < 4; j++) s[i][j] = 0.f;

        for (int c = 0; c < 64; c += 4) {
            float4 a[4], b[4];
#pragma unroll
            for (int i = 0; i < 4; i++) a[i] = *(const float4*)&Qs[(ty + 16 * i) * FPAD + c];
#pragma unroll
            for (int j = 0; j < 4; j++) b[j] = *(const float4*)&Ks[(tx + 16 * j) * FPAD + c];
#pragma unroll
            for (int i = 0; i < 4; i++)
#pragma unroll
                for (int j = 0; j < 4; j++)
                    s[i][j] += a[i].x * b[j].x + a[i].y * b[j].y +
                               a[i].z * b[j].z + a[i].w * b[j].w;
        }

        const bool diag = (kb == qb);
#pragma unroll
        for (int i = 0; i < 4; i++)
#pragma unroll
            for (int j = 0; j < 4; j++) {
                s[i][j] *= 0.125f;  // 1/sqrt(64)
                if (diag && (tx + 16 * j > ty + 16 * i)) s[i][j] = -1e30f;
            }

        // Online softmax per row; row group = 16 lanes sharing ty
#pragma unroll
        for (int i = 0; i < 4; i++) {
            float mx = fmaxf(fmaxf(s[i][0], s[i][1]), fmaxf(s[i][2], s[i][3]));
#pragma unroll
            for (int off = 8; off; off >>= 1)
                mx = fmaxf(mx, __shfl_xor_sync(0xffffffffu, mx, off));
            float mn   = fmaxf(m_i[i], mx);
            float corr = __expf(m_i[i] - mn);
            m_i[i] = mn;
            float rs = 0.f;
#pragma unroll
            for (int j = 0; j < 4; j++) { s[i][j] = __expf(s[i][j] - mn); rs += s[i][j]; }
#pragma unroll
            for (int off = 8; off; off >>= 1)
                rs += __shfl_xor_sync(0xffffffffu, rs, off);
            l_i[i] = l_i[i] * corr + rs;
#pragma unroll
            for (int j = 0; j < 4; j++) o[i][j] *= corr;
#pragma unroll
            for (int j = 0; j < 4; j++) Ps[(ty + 16 * i) * FPAD + tx + 16 * j] = s[i][j];
        }
        __syncthreads();

        // O += P V  (64x64x64)
        for (int ss = 0; ss < 64; ss += 4) {
            float4 a[4];
#pragma unroll
            for (int i = 0; i < 4; i++) a[i] = *(const float4*)&Ps[(ty + 16 * i) * FPAD + ss];
            float vb[4][4];
#pragma unroll
            for (int k2 = 0; k2 < 4; k2++)
#pragma unroll
                for (int j = 0; j < 4; j++)
                    vb[k2][j] = Vs[(ss + k2) * FPAD + tx + 16 * j];
#pragma unroll
            for (int i = 0; i < 4; i++)
#pragma unroll
                for (int j = 0; j < 4; j++)
                    o[i][j] += a[i].x * vb[0][j] + a[i].y * vb[1][j] +
                               a[i].z * vb[2][j] + a[i].w * vb[3][j];
        }
    }

    // Epilogue: normalize and store [T][D] head-interleaved
#pragma unroll
    for (int i = 0; i < 4; i++) {
        float inv = 1.0f / l_i[i];
#pragma unroll
        for (int j = 0; j < 4; j++)
            out[(size_t)(q0 + ty + 16 * i) * D_DIM + hcol + tx + 16 * j] = o[i][j] * inv;
    }
}

// ---------------------------------------------------------------------------
extern "C" void kernel_launch(void* const* d_in, const int* in_sizes, int n_in,
                              void* d_out, int out_size) {
    const float* x     = (const float*)d_in[0];  // [4096,1024]
    const float* Wqkv  = (const float*)d_in[1];  // [3072,1024]
    const float* Wproj = (const float*)d_in[2];  // [1024,1024]
    float* out = (float*)d_out;                  // [4096,1024]

    float* qkv; cudaGetSymbolAddress((void**)&qkv, g_qkv);
    float* att; cudaGetSymbolAddress((void**)&att, g_att);

    const int flash_smem = 4 * 64 * FPAD * (int)sizeof(float);  // 69,632 B
    cudaFuncSetAttribute(flash_attn, cudaFuncAttributeMaxDynamicSharedMemorySize, flash_smem);

    // 1) qkv = x @ W_qkv^T
    dim3 g1((3 * D_DIM) / 128, T_DIM / 128);
    sgemm_nt<<<g1, 256>>>(x, Wqkv, qkv, T_DIM, 3 * D_DIM, D_DIM);

    // 2) RoPE in place on q, k
    int total = T_DIM * H_NUM * (C_DIM / 2);
    rope_kernel<<<(total + 255) / 256, 256>>>(qkv);

    // 3) causal flash attention -> att [T][D]
    dim3 g2(T_DIM / 64, H_NUM);
    flash_attn<<<g2, 256, flash_smem>>>(qkv, att);

    // 4) out = att @ W_proj^T
    dim3 g3(D_DIM / 128, T_DIM / 128);
    sgemm_nt<<<g3, 256>>>(att, Wproj, out, T_DIM, D_DIM, D_DIM);
}

// round 4
// speedup vs baseline: 1.0351x; 1.0351x over previous
#include <cuda_runtime.h>
#include <math.h>
#include <stdint.h>

#define T_DIM 4096
#define D_DIM 1024
#define H_NUM 16
#define C_DIM 64
#define FPAD 68   // flash smem row stride (floats)
#define GS   20   // gemm smem row stride (16 floats + 4 pad)

// Scratch (allocations forbidden -> device globals)
__device__ float g_qkv[T_DIM * 3 * D_DIM];   // [T][3*D]
__device__ float g_att[T_DIM * D_DIM];       // [T][D]

// ---------------------------------------------------------------------------
// helpers
// ---------------------------------------------------------------------------
__device__ __forceinline__ float tf32r(float x) {
    uint32_t y;
    asm("cvt.rna.tf32.f32 %0, %1;" : "=r"(y) : "f"(x));
    return __uint_as_float(y);
}
__device__ __forceinline__ void mma8(float* d, const uint32_t* a, const uint32_t* b) {
    asm volatile(
        "mma.sync.aligned.m16n8k8.row.col.f32.tf32.tf32.f32 "
        "{%0,%1,%2,%3}, {%4,%5,%6,%7}, {%8,%9}, {%0,%1,%2,%3};"
        : "+f"(d[0]), "+f"(d[1]), "+f"(d[2]), "+f"(d[3])
        : "r"(a[0]), "r"(a[1]), "r"(a[2]), "r"(a[3]), "r"(b[0]), "r"(b[1]));
}
__device__ __forceinline__ uint32_t asu(float x) { return __float_as_uint(x); }

// ===========================================================================
// mma.sync tf32 GEMM, 3xTF32 compensated: C[M,N] = A[M,K] * B[N,K]^T (fp32 io)
// 128x128 CTA tile, K-chunk 16, 256 threads (8 warps of 64x32).
// hi/lo split done at smem-store time; fragment reads are plain LDS.
// Requires M%128==0, N%128==0, K%16==0.
// ===========================================================================
__global__ void __launch_bounds__(256) gemm_mma_tf32x3(
    const float* __restrict__ A, const float* __restrict__ B, float* __restrict__ C,
    int M, int N, int K)
{
    __shared__ float sAh[128 * GS];
    __shared__ float sAl[128 * GS];
    __shared__ float sBh[128 * GS];
    __shared__ float sBl[128 * GS];

    const int tid  = threadIdx.x;
    const int lane = tid & 31;
    const int wid  = tid >> 5;
    const int wm   = wid >> 2;     // 0..1  -> m offset 64*wm
    const int wn   = wid & 3;      // 0..3  -> n offset 32*wn
    const int bm   = blockIdx.y * 128;
    const int bn   = blockIdx.x * 128;

    // gmem load mapping: idx = tid + 256*i (i=0,1) -> row = idx>>2, colgrp = idx&3
    const int r0g = (tid + 0)   >> 2, c0g = ((tid + 0)   & 3) * 4;
    const int r1g = (tid + 256) >> 2, c1g = ((tid + 256) & 3) * 4;
    const float* A0 = A + (size_t)(bm + r0g) * K + c0g;
    const float* A1 = A + (size_t)(bm + r1g) * K + c1g;
    const float* B0 = B + (size_t)(bn + r0g) * K + c0g;
    const float* B1 = B + (size_t)(bn + r1g) * K + c1g;
    const int sa0 = r0g * GS + c0g, sa1 = r1g * GS + c1g;

    float acc[4][4][4];
#pragma unroll
    for (int i = 0; i < 4; i++)
#pragma unroll
        for (int j = 0; j < 4; j++)
#pragma unroll
            for (int k = 0; k < 4; k++) acc[i][j][k] = 0.f;

    const int nch = K >> 4;  // K/16
    float4 ra0 = *(const float4*)A0, ra1 = *(const float4*)A1;
    float4 rb0 = *(const float4*)B0, rb1 = *(const float4*)B1;

    for (int c = 0; c < nch; c++) {
        // split hi/lo and store to smem
        {
            float4 h, l;
            h.x = tf32r(ra0.x); h.y = tf32r(ra0.y); h.z = tf32r(ra0.z); h.w = tf32r(ra0.w);
            l.x = tf32r(ra0.x - h.x); l.y = tf32r(ra0.y - h.y);
            l.z = tf32r(ra0.z - h.z); l.w = tf32r(ra0.w - h.w);
            *(float4*)&sAh[sa0] = h; *(float4*)&sAl[sa0] = l;
            h.x = tf32r(ra1.x); h.y = tf32r(ra1.y); h.z = tf32r(ra1.z); h.w = tf32r(ra1.w);
            l.x = tf32r(ra1.x - h.x); l.y = tf32r(ra1.y - h.y);
            l.z = tf32r(ra1.z - h.z); l.w = tf32r(ra1.w - h.w);
            *(float4*)&sAh[sa1] = h; *(float4*)&sAl[sa1] = l;
            h.x = tf32r(rb0.x); h.y = tf32r(rb0.y); h.z = tf32r(rb0.z); h.w = tf32r(rb0.w);
            l.x = tf32r(rb0.x - h.x); l.y = tf32r(rb0.y - h.y);
            l.z = tf32r(rb0.z - h.z); l.w = tf32r(rb0.w - h.w);
            *(float4*)&sBh[sa0] = h; *(float4*)&sBl[sa0] = l;
            h.x = tf32r(rb1.x); h.y = tf32r(rb1.y); h.z = tf32r(rb1.z); h.w = tf32r(rb1.w);
            l.x = tf32r(rb1.x - h.x); l.y = tf32r(rb1.y - h.y);
            l.z = tf32r(rb1.z - h.z); l.w = tf32r(rb1.w - h.w);
            *(float4*)&sBh[sa1] = h; *(float4*)&sBl[sa1] = l;
        }
        __syncthreads();

        // prefetch next chunk into registers (hidden behind mma)
        if (c + 1 < nch) {
            const int off = (c + 1) * 16;
            ra0 = *(const float4*)(A0 + off); ra1 = *(const float4*)(A1 + off);
            rb0 = *(const float4*)(B0 + off); rb1 = *(const float4*)(B1 + off);
        }

        // compute: 2 k8 steps
#pragma unroll
        for (int ks = 0; ks < 2; ks++) {
            const int kc = ks * 8 + (lane & 3);
            uint32_t ah[4][4], al[4][4], bh[4][2], bl[4][2];
#pragma unroll
            for (int mt = 0; mt < 4; mt++) {
                const int r = (wm * 64 + mt * 16 + (lane >> 2)) * GS;
                ah[mt][0] = asu(sAh[r + kc]);          ah[mt][1] = asu(sAh[r + 8 * GS + kc]);
                ah[mt][2] = asu(sAh[r + kc + 4]);      ah[mt][3] = asu(sAh[r + 8 * GS + kc + 4]);
                al[mt][0] = asu(sAl[r + kc]);          al[mt][1] = asu(sAl[r + 8 * GS + kc]);
                al[mt][2] = asu(sAl[r + kc + 4]);      al[mt][3] = asu(sAl[r + 8 * GS + kc + 4]);
            }
#pragma unroll
            for (int nt = 0; nt < 4; nt++) {
                const int r = (wn * 32 + nt * 8 + (lane >> 2)) * GS;
                bh[nt][0] = asu(sBh[r + kc]); bh[nt][1] = asu(sBh[r + kc + 4]);
                bl[nt][0] = asu(sBl[r + kc]); bl[nt][1] = asu(sBl[r + kc + 4]);
            }
#pragma unroll
            for (int mt = 0; mt < 4; mt++)
#pragma unroll
                for (int nt = 0; nt < 4; nt++) {
                    mma8(acc[mt][nt], ah[mt], bh[nt]);
                    mma8(acc[mt][nt], ah[mt], bl[nt]);
                    mma8(acc[mt][nt], al[mt], bh[nt]);
                }
        }
        __syncthreads();
    }

    // epilogue
#pragma unroll
    for (int mt = 0; mt < 4; mt++) {
        const int row = bm + wm * 64 + mt * 16 + (lane >> 2);
#pragma unroll
        for (int nt = 0; nt < 4; nt++) {
            const int col = bn + wn * 32 + nt * 8 + 2 * (lane & 3);
            *(float2*)&C[(size_t)row * N + col] =
                make_float2(acc[mt][nt][0], acc[mt][nt][1]);
            *(float2*)&C[(size_t)(row + 8) * N + col] =
                make_float2(acc[mt][nt][2], acc[mt][nt][3]);
        }
    }
}

// ---------------------------------------------------------------------------
// RoPE in place on q,k inside g_qkv [T][3*D]
// ---------------------------------------------------------------------------
__global__ void rope_kernel(float* __restrict__ qkv) {
    int idx = blockIdx.x * blockDim.x + threadIdx.x;
    if (idx >= T_DIM * H_NUM * (C_DIM / 2)) return;
    int t = idx >> 9;
    int r = idx & 511;
    int h = r >> 5;
    int p = r & 31;

    float inv_freq = expf(-(float)p * (logf(10000.0f) / 32.0f));
    float ang = (float)t * inv_freq;
    float s, c;
    sincosf(ang, &s, &c);

    size_t base_q = (size_t)t * (3 * D_DIM) + h * C_DIM + 2 * p;
    size_t base_k = base_q + D_DIM;

    float x1 = qkv[base_q], x2 = qkv[base_q + 1];
    qkv[base_q]     = x1 * c - x2 * s;
    qkv[base_q + 1] = x2 * c + x1 * s;

    float y1 = qkv[base_k], y2 = qkv[base_k + 1];
    qkv[base_k]     = y1 * c - y2 * s;
    qkv[base_k + 1] = y2 * c + y1 * s;
}

// ---------------------------------------------------------------------------
// Flash attention, fp32, causal. Bq=Bk=64, C=64, 256 threads. (unchanged)
// ---------------------------------------------------------------------------
__global__ void flash_attn(const float* __restrict__ qkv, float* __restrict__ out) {
    extern __shared__ float smf[];
    float* Qs = smf;
    float* Ks = smf + 64 * FPAD;
    float* Vs = smf + 2 * 64 * FPAD;
    float* Ps = smf + 3 * 64 * FPAD;

    const int h   = blockIdx.y;
    const int qb  = gridDim.x - 1 - blockIdx.x;
    const int q0  = qb * 64;
    const int tid = threadIdx.x;
    const int tx  = tid & 15;
    const int ty  = tid >> 4;
    const int hcol = h * C_DIM;

    {
        int r  = tid >> 4;
        int c4 = (tid & 15) * 4;
#pragma unroll
        for (int rr = 0; rr < 64; rr += 16)
            *(float4*)&Qs[(r + rr) * FPAD + c4] =
                *(const float4*)&qkv[(size_t)(q0 + r + rr) * (3 * D_DIM) + hcol + c4];
    }

    float m_i[4], l_i[4], o[4][4];
#pragma unroll
    for (int i = 0; i < 4; i++) {
        m_i[i] = -1e30f; l_i[i] = 0.f;
#pragma unroll
        for (int j = 0; j < 4; j++) o[i][j] = 0.f;
    }

    for (int kb = 0; kb <= qb; kb++) {
        const int k0 = kb * 64;
        __syncthreads();

        {
            int r  = tid >> 4;
            int c4 = (tid & 15) * 4;
#pragma unroll
            for (int rr = 0; rr < 64; rr += 16) {
                const float* src = &qkv[(size_t)(k0 + r + rr) * (3 * D_DIM) + hcol + c4];
                *(float4*)&Ks[(r + rr) * FPAD + c4] = *(const float4*)(src + D_DIM);
                *(float4*)&Vs[(r + rr) * FPAD + c4] = *(const float4*)(src + 2 * D_DIM);
            }
        }
        __syncthreads();

        float s[4][4];
#pragma unroll
        for (int i = 0; i < 4; i++)
#pragma unroll
            for (int j = 0; j < 4; j++) s[i][j] = 0.f;

        for (int c = 0; c < 64; c += 4) {
            float4 a[4], b[4];
#pragma unroll
            for (int i = 0; i < 4; i++) a[i] = *(const float4*)&Qs[(ty + 16 * i) * FPAD + c];
#pragma unroll
            for (int j = 0; j < 4; j++) b[j] = *(const float4*)&Ks[(tx + 16 * j) * FPAD + c];
#pragma unroll
            for (int i = 0; i < 4; i++)
#pragma unroll
                for (int j = 0; j < 4; j++)
                    s[i][j] += a[i].x * b[j].x + a[i].y * b[j].y +
                               a[i].z * b[j].z + a[i].w * b[j].w;
        }

        const bool diag = (kb == qb);
#pragma unroll
        for (int i = 0; i < 4; i++)
#pragma unroll
            for (int j = 0; j < 4; j++) {
                s[i][j] *= 0.125f;
                if (diag && (tx + 16 * j > ty + 16 * i)) s[i][j] = -1e30f;
            }

#pragma unroll
        for (int i = 0; i < 4; i++) {
            float mx = fmaxf(fmaxf(s[i][0], s[i][1]), fmaxf(s[i][2], s[i][3]));
#pragma unroll
            for (int off = 8; off; off >>= 1)
                mx = fmaxf(mx, __shfl_xor_sync(0xffffffffu, mx, off));
            float mn   = fmaxf(m_i[i], mx);
            float corr = __expf(m_i[i] - mn);
            m_i[i] = mn;
            float rs = 0.f;
#pragma unroll
            for (int j = 0; j < 4; j++) { s[i][j] = __expf(s[i][j] - mn); rs += s[i][j]; }
#pragma unroll
            for (int off = 8; off; off >>= 1)
                rs += __shfl_xor_sync(0xffffffffu, rs, off);
            l_i[i] = l_i[i] * corr + rs;
#pragma unroll
            for (int j = 0; j < 4; j++) o[i][j] *= corr;
#pragma unroll
            for (int j = 0; j < 4; j++) Ps[(ty + 16 * i) * FPAD + tx + 16 * j] = s[i][j];
        }
        __syncthreads();

        for (int ss = 0; ss < 64; ss += 4) {
            float4 a[4];
#pragma unroll
            for (int i = 0; i < 4; i++) a[i] = *(const float4*)&Ps[(ty + 16 * i) * FPAD + ss];
            float vb[4][4];
#pragma unroll
            for (int k2 = 0; k2 < 4; k2++)
#pragma unroll
                for (int j = 0; j < 4; j++)
                    vb[k2][j] = Vs[(ss + k2) * FPAD + tx + 16 * j];
#pragma unroll
            for (int i = 0; i < 4; i++)
#pragma unroll
                for (int j = 0; j < 4; j++)
                    o[i][j] += a[i].x * vb[0][j] + a[i].y * vb[1][j] +
                               a[i].z * vb[2][j] + a[i].w * vb[3][j];
        }
    }

#pragma unroll
    for (int i = 0; i < 4; i++) {
        float inv = 1.0f / l_i[i];
#pragma unroll
        for (int j = 0; j < 4; j++)
            out[(size_t)(q0 + ty + 16 * i) * D_DIM + hcol + tx + 16 * j] = o[i][j] * inv;
    }
}

// ---------------------------------------------------------------------------
extern "C" void kernel_launch(void* const* d_in, const int* in_sizes, int n_in,
                              void* d_out, int out_size) {
    const float* x     = (const float*)d_in[0];  // [4096,1024]
    const float* Wqkv  = (const float*)d_in[1];  // [3072,1024]
    const float* Wproj = (const float*)d_in[2];  // [1024,1024]
    float* out = (float*)d_out;                  // [4096,1024]

    float* qkv; cudaGetSymbolAddress((void**)&qkv, g_qkv);
    float* att; cudaGetSymbolAddress((void**)&att, g_att);

    const int flash_smem = 4 * 64 * FPAD * (int)sizeof(float);  // 69,632 B
    cudaFuncSetAttribute(flash_attn, cudaFuncAttributeMaxDynamicSharedMemorySize, flash_smem);

    // 1) qkv = x @ W_qkv^T  (mma.sync tf32 x3)
    dim3 g1((3 * D_DIM) / 128, T_DIM / 128);
    gemm_mma_tf32x3<<<g1, 256>>>(x, Wqkv, qkv, T_DIM, 3 * D_DIM, D_DIM);

    // 2) RoPE in place on q, k
    int total = T_DIM * H_NUM * (C_DIM / 2);
    rope_kernel<<<(total + 255) / 256, 256>>>(qkv);

    // 3) causal flash attention -> att [T][D]
    dim3 g2(T_DIM / 64, H_NUM);
    flash_attn<<<g2, 256, flash_smem>>>(qkv, att);

    // 4) out = att @ W_proj^T  (mma.sync tf32 x3)
    dim3 g3(D_DIM / 128, T_DIM / 128);
    gemm_mma_tf32x3<<<g3, 256>>>(att, Wproj, out, T_DIM, D_DIM, D_DIM);
}

// round 7
// speedup vs baseline: 1.3426x; 1.2971x over previous
#include <cuda_runtime.h>
#include <math.h>
#include <stdint.h>

#define T_DIM 4096
#define D_DIM 1024
#define H_NUM 16
#define C_DIM 64
#define GS   20   // gemm smem row stride (16 floats + 4 pad)
#define FS   68   // flash smem row stride (64 floats + 4 pad)

// Scratch (allocations forbidden -> device globals)
__device__ float g_qkv[T_DIM * 3 * D_DIM];   // [T][3*D]
__device__ float g_att[T_DIM * D_DIM];       // [T][D]

// ---------------------------------------------------------------------------
// helpers
// ---------------------------------------------------------------------------
__device__ __forceinline__ float tf32r(float x) {
    uint32_t y;
    asm("cvt.rna.tf32.f32 %0, %1;" : "=r"(y) : "f"(x));
    return __uint_as_float(y);
}
__device__ __forceinline__ void mma8(float* d, const uint32_t* a, const uint32_t* b) {
    asm volatile(
        "mma.sync.aligned.m16n8k8.row.col.f32.tf32.tf32.f32 "
        "{%0,%1,%2,%3}, {%4,%5,%6,%7}, {%8,%9}, {%0,%1,%2,%3};"
        : "+f"(d[0]), "+f"(d[1]), "+f"(d[2]), "+f"(d[3])
        : "r"(a[0]), "r"(a[1]), "r"(a[2]), "r"(a[3]), "r"(b[0]), "r"(b[1]));
}
__device__ __forceinline__ uint32_t asu(float x) { return __float_as_uint(x); }

// ===========================================================================
// mma.sync tf32 GEMM, 3xTF32 compensated (unchanged from R4, passing)
// ===========================================================================
__global__ void __launch_bounds__(256) gemm_mma_tf32x3(
    const float* __restrict__ A, const float* __restrict__ B, float* __restrict__ C,
    int M, int N, int K)
{
    __shared__ float sAh[128 * GS];
    __shared__ float sAl[128 * GS];
    __shared__ float sBh[128 * GS];
    __shared__ float sBl[128 * GS];

    const int tid  = threadIdx.x;
    const int lane = tid & 31;
    const int wid  = tid >> 5;
    const int wm   = wid >> 2;
    const int wn   = wid & 3;
    const int bm   = blockIdx.y * 128;
    const int bn   = blockIdx.x * 128;

    const int r0g = (tid + 0)   >> 2, c0g = ((tid + 0)   & 3) * 4;
    const int r1g = (tid + 256) >> 2, c1g = ((tid + 256) & 3) * 4;
    const float* A0 = A + (size_t)(bm + r0g) * K + c0g;
    const float* A1 = A + (size_t)(bm + r1g) * K + c1g;
    const float* B0 = B + (size_t)(bn + r0g) * K + c0g;
    const float* B1 = B + (size_t)(bn + r1g) * K + c1g;
    const int sa0 = r0g * GS + c0g, sa1 = r1g * GS + c1g;

    float acc[4][4][4];
#pragma unroll
    for (int i = 0; i < 4; i++)
#pragma unroll
        for (int j = 0; j < 4; j++)
#pragma unroll
            for (int k = 0; k < 4; k++) acc[i][j][k] = 0.f;

    const int nch = K >> 4;
    float4 ra0 = *(const float4*)A0, ra1 = *(const float4*)A1;
    float4 rb0 = *(const float4*)B0, rb1 = *(const float4*)B1;

    for (int c = 0; c < nch; c++) {
        {
            float4 h, l;
            h.x = tf32r(ra0.x); h.y = tf32r(ra0.y); h.z = tf32r(ra0.z); h.w = tf32r(ra0.w);
            l.x = tf32r(ra0.x - h.x); l.y = tf32r(ra0.y - h.y);
            l.z = tf32r(ra0.z - h.z); l.w = tf32r(ra0.w - h.w);
            *(float4*)&sAh[sa0] = h; *(float4*)&sAl[sa0] = l;
            h.x = tf32r(ra1.x); h.y = tf32r(ra1.y); h.z = tf32r(ra1.z); h.w = tf32r(ra1.w);
            l.x = tf32r(ra1.x - h.x); l.y = tf32r(ra1.y - h.y);
            l.z = tf32r(ra1.z - h.z); l.w = tf32r(ra1.w - h.w);
            *(float4*)&sAh[sa1] = h; *(float4*)&sAl[sa1] = l;
            h.x = tf32r(rb0.x); h.y = tf32r(rb0.y); h.z = tf32r(rb0.z); h.w = tf32r(rb0.w);
            l.x = tf32r(rb0.x - h.x); l.y = tf32r(rb0.y - h.y);
            l.z = tf32r(rb0.z - h.z); l.w = tf32r(rb0.w - h.w);
            *(float4*)&sBh[sa0] = h; *(float4*)&sBl[sa0] = l;
            h.x = tf32r(rb1.x); h.y = tf32r(rb1.y); h.z = tf32r(rb1.z); h.w = tf32r(rb1.w);
            l.x = tf32r(rb1.x - h.x); l.y = tf32r(rb1.y - h.y);
            l.z = tf32r(rb1.z - h.z); l.w = tf32r(rb1.w - h.w);
            *(float4*)&sBh[sa1] = h; *(float4*)&sBl[sa1] = l;
        }
        __syncthreads();

        if (c + 1 < nch) {
            const int off = (c + 1) * 16;
            ra0 = *(const float4*)(A0 + off); ra1 = *(const float4*)(A1 + off);
            rb0 = *(const float4*)(B0 + off); rb1 = *(const float4*)(B1 + off);
        }

#pragma unroll
        for (int ks = 0; ks < 2; ks++) {
            const int kc = ks * 8 + (lane & 3);
            uint32_t ah[4][4], al[4][4], bh[4][2], bl[4][2];
#pragma unroll
            for (int mt = 0; mt < 4; mt++) {
                const int r = (wm * 64 + mt * 16 + (lane >> 2)) * GS;
                ah[mt][0] = asu(sAh[r + kc]);          ah[mt][1] = asu(sAh[r + 8 * GS + kc]);
                ah[mt][2] = asu(sAh[r + kc + 4]);      ah[mt][3] = asu(sAh[r + 8 * GS + kc + 4]);
                al[mt][0] = asu(sAl[r + kc]);          al[mt][1] = asu(sAl[r + 8 * GS + kc]);
                al[mt][2] = asu(sAl[r + kc + 4]);      al[mt][3] = asu(sAl[r + 8 * GS + kc + 4]);
            }
#pragma unroll
            for (int nt = 0; nt < 4; nt++) {
                const int r = (wn * 32 + nt * 8 + (lane >> 2)) * GS;
                bh[nt][0] = asu(sBh[r + kc]); bh[nt][1] = asu(sBh[r + kc + 4]);
                bl[nt][0] = asu(sBl[r + kc]); bl[nt][1] = asu(sBl[r + kc + 4]);
            }
#pragma unroll
            for (int mt = 0; mt < 4; mt++)
#pragma unroll
                for (int nt = 0; nt < 4; nt++) {
                    mma8(acc[mt][nt], ah[mt], bh[nt]);
                    mma8(acc[mt][nt], ah[mt], bl[nt]);
                    mma8(acc[mt][nt], al[mt], bh[nt]);
                }
        }
        __syncthreads();
    }

#pragma unroll
    for (int mt = 0; mt < 4; mt++) {
        const int row = bm + wm * 64 + mt * 16 + (lane >> 2);
#pragma unroll
        for (int nt = 0; nt < 4; nt++) {
            const int col = bn + wn * 32 + nt * 8 + 2 * (lane & 3);
            *(float2*)&C[(size_t)row * N + col] =
                make_float2(acc[mt][nt][0], acc[mt][nt][1]);
            *(float2*)&C[(size_t)(row + 8) * N + col] =
                make_float2(acc[mt][nt][2], acc[mt][nt][3]);
        }
    }
}

// ---------------------------------------------------------------------------
// RoPE in place on q,k inside g_qkv [T][3*D]
// ---------------------------------------------------------------------------
__global__ void rope_kernel(float* __restrict__ qkv) {
    int idx = blockIdx.x * blockDim.x + threadIdx.x;
    if (idx >= T_DIM * H_NUM * (C_DIM / 2)) return;
    int t = idx >> 9;
    int r = idx & 511;
    int h = r >> 5;
    int p = r & 31;

    float inv_freq = expf(-(float)p * (logf(10000.0f) / 32.0f));
    float ang = (float)t * inv_freq;
    float s, c;
    sincosf(ang, &s, &c);

    size_t base_q = (size_t)t * (3 * D_DIM) + h * C_DIM + 2 * p;
    size_t base_k = base_q + D_DIM;

    float x1 = qkv[base_q], x2 = qkv[base_q + 1];
    qkv[base_q]     = x1 * c - x2 * s;
    qkv[base_q + 1] = x2 * c + x1 * s;

    float y1 = qkv[base_k], y2 = qkv[base_k + 1];
    qkv[base_k]     = y1 * c - y2 * s;
    qkv[base_k + 1] = y2 * c + y1 * s;
}

// ===========================================================================
// Tensor-core flash attention, causal, 3xTF32 everywhere.
// Bq=128, Bk=64, C=64, 256 threads / 8 warps.
// Warp w owns S/O rows 16w..16w+15 x all 64 cols -> softmax warp-local.
// smem: Qh Ql [128*FS], Kh Kl [64*FS], VhT VlT [64*FS] (transposed),
//       Psh Psl [128*FS]  => 204 KB
// ===========================================================================
#define FA_SMEM ((2 * 128 * FS + 2 * 64 * FS + 2 * 64 * FS + 2 * 128 * FS) * 4)

__global__ void __launch_bounds__(256) flash_attn_tc(
    const float* __restrict__ qkv, float* __restrict__ out)
{
    extern __shared__ float smf[];
    float* Qh  = smf;
    float* Ql  = Qh + 128 * FS;
    float* Kh  = Ql + 128 * FS;
    float* Kl  = Kh + 64 * FS;
    float* Vh  = Kl + 64 * FS;   // V^T: [c][s]
    float* Vl  = Vh + 64 * FS;
    float* Psh = Vl + 64 * FS;
    float* Psl = Psh + 128 * FS;

    const int h    = blockIdx.y;
    const int qb   = gridDim.x - 1 - blockIdx.x;   // big blocks first
    const int q0   = qb * 128;
    const int tid  = threadIdx.x;
    const int lane = tid & 31;
    const int wid  = tid >> 5;
    const int hcol = h * C_DIM;
    const int row0 = wid * 16 + (lane >> 2);       // local S/O row of c0,c1

    // --- load Q tile [128][64], split hi/lo ---
#pragma unroll
    for (int i = 0; i < 8; i++) {
        int idx = tid + 256 * i;
        int r = idx >> 4, c4 = (idx & 15) * 4;
        float4 v = *(const float4*)&qkv[(size_t)(q0 + r) * (3 * D_DIM) + hcol + c4];
        float4 hh, ll;
        hh.x = tf32r(v.x); hh.y = tf32r(v.y); hh.z = tf32r(v.z); hh.w = tf32r(v.w);
        ll.x = tf32r(v.x - hh.x); ll.y = tf32r(v.y - hh.y);
        ll.z = tf32r(v.z - hh.z); ll.w = tf32r(v.w - hh.w);
        *(float4*)&Qh[r * FS + c4] = hh;
        *(float4*)&Ql[r * FS + c4] = ll;
    }

    float m0 = -1e30f, m1 = -1e30f, l0 = 0.f, l1 = 0.f;
    float oacc[8][4];
#pragma unroll
    for (int nt = 0; nt < 8; nt++)
#pragma unroll
        for (int j = 0; j < 4; j++) oacc[nt][j] = 0.f;

    const int kbmax = 2 * qb + 1;
    for (int kb = 0; kb <= kbmax; kb++) {
        const int k0 = kb * 64;
        __syncthreads();  // all warps done with prior K/V

        // --- load K [64][64] and V^T [64][64], split hi/lo ---
#pragma unroll
        for (int i = 0; i < 4; i++) {
            int idx = tid + 256 * i;
            int r = idx >> 4, c4 = (idx & 15) * 4;
            const float* src = &qkv[(size_t)(k0 + r) * (3 * D_DIM) + hcol + c4];
            float4 kv = *(const float4*)(src + D_DIM);
            float4 hh, ll;
            hh.x = tf32r(kv.x); hh.y = tf32r(kv.y); hh.z = tf32r(kv.z); hh.w = tf32r(kv.w);
            ll.x = tf32r(kv.x - hh.x); ll.y = tf32r(kv.y - hh.y);
            ll.z = tf32r(kv.z - hh.z); ll.w = tf32r(kv.w - hh.w);
            *(float4*)&Kh[r * FS + c4] = hh;
            *(float4*)&Kl[r * FS + c4] = ll;
            float4 vv = *(const float4*)(src + 2 * D_DIM);
            float vh0 = tf32r(vv.x), vh1 = tf32r(vv.y), vh2 = tf32r(vv.z), vh3 = tf32r(vv.w);
            Vh[(c4 + 0) * FS + r] = vh0; Vl[(c4 + 0) * FS + r] = tf32r(vv.x - vh0);
            Vh[(c4 + 1) * FS + r] = vh1; Vl[(c4 + 1) * FS + r] = tf32r(vv.y - vh1);
            Vh[(c4 + 2) * FS + r] = vh2; Vl[(c4 + 2) * FS + r] = tf32r(vv.z - vh2);
            Vh[(c4 + 3) * FS + r] = vh3; Vl[(c4 + 3) * FS + r] = tf32r(vv.w - vh3);
        }
        __syncthreads();

        // --- S = Q K^T, 3xTF32 ---
        float sacc[8][4];
#pragma unroll
        for (int nt = 0; nt < 8; nt++)
#pragma unroll
            for (int j = 0; j < 4; j++) sacc[nt][j] = 0.f;

#pragma unroll
        for (int ks = 0; ks < 8; ks++) {
            const int kc = ks * 8 + (lane & 3);
            const int ar = row0 * FS;
            uint32_t ah[4], al[4];
            ah[0] = asu(Qh[ar + kc]);            ah[1] = asu(Qh[ar + 8 * FS + kc]);
            ah[2] = asu(Qh[ar + kc + 4]);        ah[3] = asu(Qh[ar + 8 * FS + kc + 4]);
            al[0] = asu(Ql[ar + kc]);            al[1] = asu(Ql[ar + 8 * FS + kc]);
            al[2] = asu(Ql[ar + kc + 4]);        al[3] = asu(Ql[ar + 8 * FS + kc + 4]);
#pragma unroll
            for (int nt = 0; nt < 8; nt++) {
                const int br = (nt * 8 + (lane >> 2)) * FS;
                uint32_t bh[2] = { asu(Kh[br + kc]), asu(Kh[br + kc + 4]) };
                uint32_t bl[2] = { asu(Kl[br + kc]), asu(Kl[br + kc + 4]) };
                mma8(sacc[nt], ah, bh);
                mma8(sacc[nt], ah, bl);
                mma8(sacc[nt], al, bh);
            }
        }

        // --- scale + causal mask ---
        const bool mb = (kb >= 2 * qb);
        const int lim = q0 - k0;   // keep col c if c <= row + lim
        float mx0 = -1e30f, mx1 = -1e30f;
#pragma unroll
        for (int nt = 0; nt < 8; nt++) {
            const int cb = nt * 8 + 2 * (lane & 3);
#pragma unroll
            for (int j = 0; j < 2; j++) {
                float v0 = sacc[nt][j] * 0.125f;
                float v1 = sacc[nt][2 + j] * 0.125f;
                if (mb) {
                    if (cb + j > row0 + lim)     v0 = -1e30f;
                    if (cb + j > row0 + 8 + lim) v1 = -1e30f;
                }
                sacc[nt][j] = v0; sacc[nt][2 + j] = v1;
                mx0 = fmaxf(mx0, v0); mx1 = fmaxf(mx1, v1);
            }
        }
        mx0 = fmaxf(mx0, __shfl_xor_sync(0xffffffffu, mx0, 1));
        mx0 = fmaxf(mx0, __shfl_xor_sync(0xffffffffu, mx0, 2));
        mx1 = fmaxf(mx1, __shfl_xor_sync(0xffffffffu, mx1, 1));
        mx1 = fmaxf(mx1, __shfl_xor_sync(0xffffffffu, mx1, 2));

        const float nm0 = fmaxf(m0, mx0), nm1 = fmaxf(m1, mx1);
        const float corr0 = __expf(m0 - nm0), corr1 = __expf(m1 - nm1);
        m0 = nm0; m1 = nm1;

        float rs0 = 0.f, rs1 = 0.f;
#pragma unroll
        for (int nt = 0; nt < 8; nt++) {
            const int cb = nt * 8 + 2 * (lane & 3);
            float p0 = __expf(sacc[nt][0] - nm0);
            float p1 = __expf(sacc[nt][1] - nm0);
            float p2 = __expf(sacc[nt][2] - nm1);
            float p3 = __expf(sacc[nt][3] - nm1);
            rs0 += p0 + p1; rs1 += p2 + p3;
            float h0 = tf32r(p0), h1 = tf32r(p1), h2 = tf32r(p2), h3 = tf32r(p3);
            *(float2*)&Psh[row0 * FS + cb]       = make_float2(h0, h1);
            *(float2*)&Psl[row0 * FS + cb]       = make_float2(tf32r(p0 - h0), tf32r(p1 - h1));
            *(float2*)&Psh[(row0 + 8) * FS + cb] = make_float2(h2, h3);
            *(float2*)&Psl[(row0 + 8) * FS + cb] = make_float2(tf32r(p2 - h2), tf32r(p3 - h3));
        }
        rs0 += __shfl_xor_sync(0xffffffffu, rs0, 1);
        rs0 += __shfl_xor_sync(0xffffffffu, rs0, 2);
        rs1 += __shfl_xor_sync(0xffffffffu, rs1, 1);
        rs1 += __shfl_xor_sync(0xffffffffu, rs1, 2);
        l0 = l0 * corr0 + rs0;
        l1 = l1 * corr1 + rs1;

#pragma unroll
        for (int nt = 0; nt < 8; nt++) {
            oacc[nt][0] *= corr0; oacc[nt][1] *= corr0;
            oacc[nt][2] *= corr1; oacc[nt][3] *= corr1;
        }
        __syncwarp();   // P tile is warp-private (rows 16w..16w+15)

        // --- O += P V, 3xTF32 ---
#pragma unroll
        for (int ks = 0; ks < 8; ks++) {
            const int kc = ks * 8 + (lane & 3);
            const int ar = row0 * FS;
            uint32_t ph[4], pl[4];
            ph[0] = asu(Psh[ar + kc]);            ph[1] = asu(Psh[ar + 8 * FS + kc]);
            ph[2] = asu(Psh[ar + kc + 4]);        ph[3] = asu(Psh[ar + 8 * FS + kc + 4]);
            pl[0] = asu(Psl[ar + kc]);            pl[1] = asu(Psl[ar + 8 * FS + kc]);
            pl[2] = asu(Psl[ar + kc + 4]);        pl[3] = asu(Psl[ar + 8 * FS + kc + 4]);
#pragma unroll
            for (int nt = 0; nt < 8; nt++) {
                const int br = (nt * 8 + (lane >> 2)) * FS;
                uint32_t vh2[2] = { asu(Vh[br + kc]), asu(Vh[br + kc + 4]) };
                uint32_t vl2[2] = { asu(Vl[br + kc]), asu(Vl[br + kc + 4]) };
                mma8(oacc[nt], ph, vh2);
                mma8(oacc[nt], ph, vl2);
                mma8(oacc[nt], pl, vh2);
            }
        }
        __syncwarp();   // done reading warp-private P before next overwrite
    }

    // --- epilogue: normalize, store [T][D] ---
    const float inv0 = 1.0f / l0, inv1 = 1.0f / l1;
#pragma unroll
    for (int nt = 0; nt < 8; nt++) {
        const int cb = hcol + nt * 8 + 2 * (lane & 3);
        *(float2*)&out[(size_t)(q0 + row0) * D_DIM + cb] =
            make_float2(oacc[nt][0] * inv0, oacc[nt][1] * inv0);
        *(float2*)&out[(size_t)(q0 + row0 + 8) * D_DIM + cb] =
            make_float2(oacc[nt][2] * inv1, oacc[nt][3] * inv1);
    }
}

// ---------------------------------------------------------------------------
extern "C" void kernel_launch(void* const* d_in, const int* in_sizes, int n_in,
                              void* d_out, int out_size) {
    const float* x     = (const float*)d_in[0];  // [4096,1024]
    const float* Wqkv  = (const float*)d_in[1];  // [3072,1024]
    const float* Wproj = (const float*)d_in[2];  // [1024,1024]
    float* out = (float*)d_out;                  // [4096,1024]

    float* qkv; cudaGetSymbolAddress((void**)&qkv, g_qkv);
    float* att; cudaGetSymbolAddress((void**)&att, g_att);

    cudaFuncSetAttribute(flash_attn_tc, cudaFuncAttributeMaxDynamicSharedMemorySize, FA_SMEM);

    // 1) qkv = x @ W_qkv^T
    dim3 g1((3 * D_DIM) / 128, T_DIM / 128);
    gemm_mma_tf32x3<<<g1, 256>>>(x, Wqkv, qkv, T_DIM, 3 * D_DIM, D_DIM);

    // 2) RoPE in place on q, k
    int total = T_DIM * H_NUM * (C_DIM / 2);
    rope_kernel<<<(total + 255) / 256, 256>>>(qkv);

    // 3) causal flash attention (tensor cores) -> att [T][D]
    dim3 g2(T_DIM / 128, H_NUM);
    flash_attn_tc<<<g2, 256, FA_SMEM>>>(qkv, att);

    // 4) out = att @ W_proj^T
    dim3 g3(D_DIM / 128, T_DIM / 128);
    gemm_mma_tf32x3<<<g3, 256>>>(att, Wproj, out, T_DIM, D_DIM, D_DIM);
}

// round 8
// speedup vs baseline: 1.3444x; 1.0013x over previous
#include <cuda_runtime.h>
#include <math.h>
#include <stdint.h>

#define T_DIM 4096
#define D_DIM 1024
#define H_NUM 16
#define C_DIM 64
#define GS   20   // gemm smem row stride (16 floats + 4 pad)
#define FS   68   // flash smem row stride (64 floats + 4 pad)

// Scratch (allocations forbidden -> device globals)
__device__ float g_qkv[T_DIM * 3 * D_DIM];   // [T][3*D]
__device__ float g_att[T_DIM * D_DIM];       // [T][D]

// ---------------------------------------------------------------------------
// helpers
// ---------------------------------------------------------------------------
__device__ __forceinline__ float tf32r(float x) {
    uint32_t y;
    asm("cvt.rna.tf32.f32 %0, %1;" : "=r"(y) : "f"(x));
    return __uint_as_float(y);
}
__device__ __forceinline__ void mma8(float* d, const uint32_t* a, const uint32_t* b) {
    asm volatile(
        "mma.sync.aligned.m16n8k8.row.col.f32.tf32.tf32.f32 "
        "{%0,%1,%2,%3}, {%4,%5,%6,%7}, {%8,%9}, {%0,%1,%2,%3};"
        : "+f"(d[0]), "+f"(d[1]), "+f"(d[2]), "+f"(d[3])
        : "r"(a[0]), "r"(a[1]), "r"(a[2]), "r"(a[3]), "r"(b[0]), "r"(b[1]));
}
__device__ __forceinline__ uint32_t asu(float x) { return __float_as_uint(x); }

// ===========================================================================
// mma.sync tf32 GEMM, 3xTF32 compensated (unchanged from R4/R7, passing)
// ===========================================================================
__global__ void __launch_bounds__(256) gemm_mma_tf32x3(
    const float* __restrict__ A, const float* __restrict__ B, float* __restrict__ C,
    int M, int N, int K)
{
    __shared__ float sAh[128 * GS];
    __shared__ float sAl[128 * GS];
    __shared__ float sBh[128 * GS];
    __shared__ float sBl[128 * GS];

    const int tid  = threadIdx.x;
    const int lane = tid & 31;
    const int wid  = tid >> 5;
    const int wm   = wid >> 2;
    const int wn   = wid & 3;
    const int bm   = blockIdx.y * 128;
    const int bn   = blockIdx.x * 128;

    const int r0g = (tid + 0)   >> 2, c0g = ((tid + 0)   & 3) * 4;
    const int r1g = (tid + 256) >> 2, c1g = ((tid + 256) & 3) * 4;
    const float* A0 = A + (size_t)(bm + r0g) * K + c0g;
    const float* A1 = A + (size_t)(bm + r1g) * K + c1g;
    const float* B0 = B + (size_t)(bn + r0g) * K + c0g;
    const float* B1 = B + (size_t)(bn + r1g) * K + c1g;
    const int sa0 = r0g * GS + c0g, sa1 = r1g * GS + c1g;

    float acc[4][4][4];
#pragma unroll
    for (int i = 0; i < 4; i++)
#pragma unroll
        for (int j = 0; j < 4; j++)
#pragma unroll
            for (int k = 0; k < 4; k++) acc[i][j][k] = 0.f;

    const int nch = K >> 4;
    float4 ra0 = *(const float4*)A0, ra1 = *(const float4*)A1;
    float4 rb0 = *(const float4*)B0, rb1 = *(const float4*)B1;

    for (int c = 0; c < nch; c++) {
        {
            float4 h, l;
            h.x = tf32r(ra0.x); h.y = tf32r(ra0.y); h.z = tf32r(ra0.z); h.w = tf32r(ra0.w);
            l.x = tf32r(ra0.x - h.x); l.y = tf32r(ra0.y - h.y);
            l.z = tf32r(ra0.z - h.z); l.w = tf32r(ra0.w - h.w);
            *(float4*)&sAh[sa0] = h; *(float4*)&sAl[sa0] = l;
            h.x = tf32r(ra1.x); h.y = tf32r(ra1.y); h.z = tf32r(ra1.z); h.w = tf32r(ra1.w);
            l.x = tf32r(ra1.x - h.x); l.y = tf32r(ra1.y - h.y);
            l.z = tf32r(ra1.z - h.z); l.w = tf32r(ra1.w - h.w);
            *(float4*)&sAh[sa1] = h; *(float4*)&sAl[sa1] = l;
            h.x = tf32r(rb0.x); h.y = tf32r(rb0.y); h.z = tf32r(rb0.z); h.w = tf32r(rb0.w);
            l.x = tf32r(rb0.x - h.x); l.y = tf32r(rb0.y - h.y);
            l.z = tf32r(rb0.z - h.z); l.w = tf32r(rb0.w - h.w);
            *(float4*)&sBh[sa0] = h; *(float4*)&sBl[sa0] = l;
            h.x = tf32r(rb1.x); h.y = tf32r(rb1.y); h.z = tf32r(rb1.z); h.w = tf32r(rb1.w);
            l.x = tf32r(rb1.x - h.x); l.y = tf32r(rb1.y - h.y);
            l.z = tf32r(rb1.z - h.z); l.w = tf32r(rb1.w - h.w);
            *(float4*)&sBh[sa1] = h; *(float4*)&sBl[sa1] = l;
        }
        __syncthreads();

        if (c + 1 < nch) {
            const int off = (c + 1) * 16;
            ra0 = *(const float4*)(A0 + off); ra1 = *(const float4*)(A1 + off);
            rb0 = *(const float4*)(B0 + off); rb1 = *(const float4*)(B1 + off);
        }

#pragma unroll
        for (int ks = 0; ks < 2; ks++) {
            const int kc = ks * 8 + (lane & 3);
            uint32_t ah[4][4], al[4][4], bh[4][2], bl[4][2];
#pragma unroll
            for (int mt = 0; mt < 4; mt++) {
                const int r = (wm * 64 + mt * 16 + (lane >> 2)) * GS;
                ah[mt][0] = asu(sAh[r + kc]);          ah[mt][1] = asu(sAh[r + 8 * GS + kc]);
                ah[mt][2] = asu(sAh[r + kc + 4]);      ah[mt][3] = asu(sAh[r + 8 * GS + kc + 4]);
                al[mt][0] = asu(sAl[r + kc]);          al[mt][1] = asu(sAl[r + 8 * GS + kc]);
                al[mt][2] = asu(sAl[r + kc + 4]);      al[mt][3] = asu(sAl[r + 8 * GS + kc + 4]);
            }
#pragma unroll
            for (int nt = 0; nt < 4; nt++) {
                const int r = (wn * 32 + nt * 8 + (lane >> 2)) * GS;
                bh[nt][0] = asu(sBh[r + kc]); bh[nt][1] = asu(sBh[r + kc + 4]);
                bl[nt][0] = asu(sBl[r + kc]); bl[nt][1] = asu(sBl[r + kc + 4]);
            }
#pragma unroll
            for (int mt = 0; mt < 4; mt++)
#pragma unroll
                for (int nt = 0; nt < 4; nt++) {
                    mma8(acc[mt][nt], ah[mt], bh[nt]);
                    mma8(acc[mt][nt], ah[mt], bl[nt]);
                    mma8(acc[mt][nt], al[mt], bh[nt]);
                }
        }
        __syncthreads();
    }

#pragma unroll
    for (int mt = 0; mt < 4; mt++) {
        const int row = bm + wm * 64 + mt * 16 + (lane >> 2);
#pragma unroll
        for (int nt = 0; nt < 4; nt++) {
            const int col = bn + wn * 32 + nt * 8 + 2 * (lane & 3);
            *(float2*)&C[(size_t)row * N + col] =
                make_float2(acc[mt][nt][0], acc[mt][nt][1]);
            *(float2*)&C[(size_t)(row + 8) * N + col] =
                make_float2(acc[mt][nt][2], acc[mt][nt][3]);
        }
    }
}

// ---------------------------------------------------------------------------
// RoPE in place on q,k inside g_qkv [T][3*D]
// ---------------------------------------------------------------------------
__global__ void rope_kernel(float* __restrict__ qkv) {
    int idx = blockIdx.x * blockDim.x + threadIdx.x;
    if (idx >= T_DIM * H_NUM * (C_DIM / 2)) return;
    int t = idx >> 9;
    int r = idx & 511;
    int h = r >> 5;
    int p = r & 31;

    float inv_freq = expf(-(float)p * (logf(10000.0f) / 32.0f));
    float ang = (float)t * inv_freq;
    float s, c;
    sincosf(ang, &s, &c);

    size_t base_q = (size_t)t * (3 * D_DIM) + h * C_DIM + 2 * p;
    size_t base_k = base_q + D_DIM;

    float x1 = qkv[base_q], x2 = qkv[base_q + 1];
    qkv[base_q]     = x1 * c - x2 * s;
    qkv[base_q + 1] = x2 * c + x1 * s;

    float y1 = qkv[base_k], y2 = qkv[base_k + 1];
    qkv[base_k]     = y1 * c - y2 * s;
    qkv[base_k + 1] = y2 * c + y1 * s;
}

// ===========================================================================
// Tensor-core flash attention, causal, 3xTF32, register-prefetch pipelined.
// Bq=128, Bk=64, C=64, 256 threads / 8 warps.
// Warp w owns S/O rows 16w..16w+15 x all 64 cols -> softmax warp-local.
// K/V for block kb+1 are prefetched into registers while computing kb.
// V loader uses column-chunk mapping -> V^T stores are conflict-free STS.128.
// ===========================================================================
#define FA_SMEM ((2 * 128 * FS + 2 * 64 * FS + 2 * 64 * FS + 2 * 128 * FS) * 4)
#define SC2 0.18033688f   // 0.125 * log2(e)

__global__ void __launch_bounds__(256) flash_attn_tc(
    const float* __restrict__ qkv, float* __restrict__ out)
{
    extern __shared__ float smf[];
    float* Qh  = smf;
    float* Ql  = Qh + 128 * FS;
    float* Kh  = Ql + 128 * FS;
    float* Kl  = Kh + 64 * FS;
    float* Vh  = Kl + 64 * FS;   // V^T: [c][s]
    float* Vl  = Vh + 64 * FS;
    float* Psh = Vl + 64 * FS;
    float* Psl = Psh + 128 * FS;

    const int h    = blockIdx.y;
    const int qb   = gridDim.x - 1 - blockIdx.x;   // big blocks first
    const int q0   = qb * 128;
    const int tid  = threadIdx.x;
    const int lane = tid & 31;
    const int wid  = tid >> 5;
    const int hcol = h * C_DIM;
    const int row0 = wid * 16 + (lane >> 2);       // local S/O row of c0,c1

    // loader mappings
    const int kr   = tid >> 4;          // K row base (idx=tid+256i -> row kr+16i)
    const int kc4  = (tid & 15) * 4;    // K col group
    const int vc   = tid & 63;          // V column (head dim c)
    const int vr4  = (tid >> 6) * 4;    // V row chunk base (idx -> vr4+16i)

    // --- load Q tile [128][64], split hi/lo ---
#pragma unroll
    for (int i = 0; i < 8; i++) {
        int idx = tid + 256 * i;
        int r = idx >> 4, c4 = (idx & 15) * 4;
        float4 v = *(const float4*)&qkv[(size_t)(q0 + r) * (3 * D_DIM) + hcol + c4];
        float4 hh, ll;
        hh.x = tf32r(v.x); hh.y = tf32r(v.y); hh.z = tf32r(v.z); hh.w = tf32r(v.w);
        ll.x = tf32r(v.x - hh.x); ll.y = tf32r(v.y - hh.y);
        ll.z = tf32r(v.z - hh.z); ll.w = tf32r(v.w - hh.w);
        *(float4*)&Qh[r * FS + c4] = hh;
        *(float4*)&Ql[r * FS + c4] = ll;
    }

    float m0 = -1e30f, m1 = -1e30f, l0 = 0.f, l1 = 0.f;
    float oacc[8][4];
#pragma unroll
    for (int nt = 0; nt < 8; nt++)
#pragma unroll
        for (int j = 0; j < 4; j++) oacc[nt][j] = 0.f;

    // prefetch registers for tile kb (K: 4 x float4, V: 16 scalars)
    float4 rk[4];
    float  rv[4][4];
    const float* kbase = qkv + 1024 + hcol + (size_t)kr * (3 * D_DIM) + kc4;
    const float* vbase = qkv + 2048 + hcol + vc;

    // prefetch kb = 0
#pragma unroll
    for (int i = 0; i < 4; i++)
        rk[i] = *(const float4*)(kbase + (size_t)(16 * i) * (3 * D_DIM));
#pragma unroll
    for (int i = 0; i < 4; i++)
#pragma unroll
        for (int j = 0; j < 4; j++)
            rv[i][j] = vbase[(size_t)(vr4 + 16 * i + j) * (3 * D_DIM)];

    const int kbmax = 2 * qb + 1;
    for (int kb = 0; kb <= kbmax; kb++) {
        __syncthreads();  // all warps done reading prior K/V smem

        // --- store prefetched tile to smem, split hi/lo ---
#pragma unroll
        for (int i = 0; i < 4; i++) {
            const int r = kr + 16 * i;
            float4 kv = rk[i];
            float4 hh, ll;
            hh.x = tf32r(kv.x); hh.y = tf32r(kv.y); hh.z = tf32r(kv.z); hh.w = tf32r(kv.w);
            ll.x = tf32r(kv.x - hh.x); ll.y = tf32r(kv.y - hh.y);
            ll.z = tf32r(kv.z - hh.z); ll.w = tf32r(kv.w - hh.w);
            *(float4*)&Kh[r * FS + kc4] = hh;
            *(float4*)&Kl[r * FS + kc4] = ll;

            float4 vh4, vl4;
            vh4.x = tf32r(rv[i][0]); vl4.x = tf32r(rv[i][0] - vh4.x);
            vh4.y = tf32r(rv[i][1]); vl4.y = tf32r(rv[i][1] - vh4.y);
            vh4.z = tf32r(rv[i][2]); vl4.z = tf32r(rv[i][2] - vh4.z);
            vh4.w = tf32r(rv[i][3]); vl4.w = tf32r(rv[i][3] - vh4.w);
            *(float4*)&Vh[vc * FS + vr4 + 16 * i] = vh4;   // V^T store, conflict-free
            *(float4*)&Vl[vc * FS + vr4 + 16 * i] = vl4;
        }
        __syncthreads();

        // --- prefetch tile kb+1 (hidden under compute below) ---
        if (kb < kbmax) {
            const size_t off = (size_t)(kb + 1) * 64 * (3 * D_DIM);
#pragma unroll
            for (int i = 0; i < 4; i++)
                rk[i] = *(const float4*)(kbase + off + (size_t)(16 * i) * (3 * D_DIM));
#pragma unroll
            for (int i = 0; i < 4; i++)
#pragma unroll
                for (int j = 0; j < 4; j++)
                    rv[i][j] = vbase[off + (size_t)(vr4 + 16 * i + j) * (3 * D_DIM)];
        }

        // --- S = Q K^T, 3xTF32 ---
        float sacc[8][4];
#pragma unroll
        for (int nt = 0; nt < 8; nt++)
#pragma unroll
            for (int j = 0; j < 4; j++) sacc[nt][j] = 0.f;

#pragma unroll
        for (int ks = 0; ks < 8; ks++) {
            const int kc = ks * 8 + (lane & 3);
            const int ar = row0 * FS;
            uint32_t ah[4], al[4];
            ah[0] = asu(Qh[ar + kc]);            ah[1] = asu(Qh[ar + 8 * FS + kc]);
            ah[2] = asu(Qh[ar + kc + 4]);        ah[3] = asu(Qh[ar + 8 * FS + kc + 4]);
            al[0] = asu(Ql[ar + kc]);            al[1] = asu(Ql[ar + 8 * FS + kc]);
            al[2] = asu(Ql[ar + kc + 4]);        al[3] = asu(Ql[ar + 8 * FS + kc + 4]);
#pragma unroll
            for (int nt = 0; nt < 8; nt++) {
                const int br = (nt * 8 + (lane >> 2)) * FS;
                uint32_t bh[2] = { asu(Kh[br + kc]), asu(Kh[br + kc + 4]) };
                uint32_t bl[2] = { asu(Kl[br + kc]), asu(Kl[br + kc + 4]) };
                mma8(sacc[nt], ah, bh);
                mma8(sacc[nt], ah, bl);
                mma8(sacc[nt], al, bh);
            }
        }

        // --- scale (log2 domain) + causal mask ---
        const bool mb = (kb >= 2 * qb);
        const int lim = q0 - kb * 64;   // keep col c if c <= row + lim
        float mx0 = -1e30f, mx1 = -1e30f;
#pragma unroll
        for (int nt = 0; nt < 8; nt++) {
            const int cb = nt * 8 + 2 * (lane & 3);
#pragma unroll
            for (int j = 0; j < 2; j++) {
                float v0 = sacc[nt][j] * SC2;
                float v1 = sacc[nt][2 + j] * SC2;
                if (mb) {
                    if (cb + j > row0 + lim)     v0 = -1e30f;
                    if (cb + j > row0 + 8 + lim) v1 = -1e30f;
                }
                sacc[nt][j] = v0; sacc[nt][2 + j] = v1;
                mx0 = fmaxf(mx0, v0); mx1 = fmaxf(mx1, v1);
            }
        }
        mx0 = fmaxf(mx0, __shfl_xor_sync(0xffffffffu, mx0, 1));
        mx0 = fmaxf(mx0, __shfl_xor_sync(0xffffffffu, mx0, 2));
        mx1 = fmaxf(mx1, __shfl_xor_sync(0xffffffffu, mx1, 1));
        mx1 = fmaxf(mx1, __shfl_xor_sync(0xffffffffu, mx1, 2));

        const float nm0 = fmaxf(m0, mx0), nm1 = fmaxf(m1, mx1);
        const float corr0 = exp2f(m0 - nm0), corr1 = exp2f(m1 - nm1);
        m0 = nm0; m1 = nm1;

        float rs0 = 0.f, rs1 = 0.f;
#pragma unroll
        for (int nt = 0; nt < 8; nt++) {
            const int cb = nt * 8 + 2 * (lane & 3);
            float p0 = exp2f(sacc[nt][0] - nm0);
            float p1 = exp2f(sacc[nt][1] - nm0);
            float p2 = exp2f(sacc[nt][2] - nm1);
            float p3 = exp2f(sacc[nt][3] - nm1);
            rs0 += p0 + p1; rs1 += p2 + p3;
            float h0 = tf32r(p0), h1 = tf32r(p1), h2 = tf32r(p2), h3 = tf32r(p3);
            *(float2*)&Psh[row0 * FS + cb]       = make_float2(h0, h1);
            *(float2*)&Psl[row0 * FS + cb]       = make_float2(tf32r(p0 - h0), tf32r(p1 - h1));
            *(float2*)&Psh[(row0 + 8) * FS + cb] = make_float2(h2, h3);
            *(float2*)&Psl[(row0 + 8) * FS + cb] = make_float2(tf32r(p2 - h2), tf32r(p3 - h3));
        }
        rs0 += __shfl_xor_sync(0xffffffffu, rs0, 1);
        rs0 += __shfl_xor_sync(0xffffffffu, rs0, 2);
        rs1 += __shfl_xor_sync(0xffffffffu, rs1, 1);
        rs1 += __shfl_xor_sync(0xffffffffu, rs1, 2);
        l0 = l0 * corr0 + rs0;
        l1 = l1 * corr1 + rs1;

#pragma unroll
        for (int nt = 0; nt < 8; nt++) {
            oacc[nt][0] *= corr0; oacc[nt][1] *= corr0;
            oacc[nt][2] *= corr1; oacc[nt][3] *= corr1;
        }
        __syncwarp();   // P tile is warp-private (rows 16w..16w+15)

        // --- O += P V, 3xTF32 ---
#pragma unroll
        for (int ks = 0; ks < 8; ks++) {
            const int kc = ks * 8 + (lane & 3);
            const int ar = row0 * FS;
            uint32_t ph[4], pl[4];
            ph[0] = asu(Psh[ar + kc]);            ph[1] = asu(Psh[ar + 8 * FS + kc]);
            ph[2] = asu(Psh[ar + kc + 4]);        ph[3] = asu(Psh[ar + 8 * FS + kc + 4]);
            pl[0] = asu(Psl[ar + kc]);            pl[1] = asu(Psl[ar + 8 * FS + kc]);
            pl[2] = asu(Psl[ar + kc + 4]);        pl[3] = asu(Psl[ar + 8 * FS + kc + 4]);
#pragma unroll
            for (int nt = 0; nt < 8; nt++) {
                const int br = (nt * 8 + (lane >> 2)) * FS;
                uint32_t vh2[2] = { asu(Vh[br + kc]), asu(Vh[br + kc + 4]) };
                uint32_t vl2[2] = { asu(Vl[br + kc]), asu(Vl[br + kc + 4]) };
                mma8(oacc[nt], ph, vh2);
                mma8(oacc[nt], ph, vl2);
                mma8(oacc[nt], pl, vh2);
            }
        }
        __syncwarp();   // done reading warp-private P before next overwrite
    }

    // --- epilogue: normalize, store [T][D] ---
    const float inv0 = 1.0f / l0, inv1 = 1.0f / l1;
#pragma unroll
    for (int nt = 0; nt < 8; nt++) {
        const int cb = hcol + nt * 8 + 2 * (lane & 3);
        *(float2*)&out[(size_t)(q0 + row0) * D_DIM + cb] =
            make_float2(oacc[nt][0] * inv0, oacc[nt][1] * inv0);
        *(float2*)&out[(size_t)(q0 + row0 + 8) * D_DIM + cb] =
            make_float2(oacc[nt][2] * inv1, oacc[nt][3] * inv1);
    }
}

// ---------------------------------------------------------------------------
extern "C" void kernel_launch(void* const* d_in, const int* in_sizes, int n_in,
                              void* d_out, int out_size) {
    const float* x     = (const float*)d_in[0];  // [4096,1024]
    const float* Wqkv  = (const float*)d_in[1];  // [3072,1024]
    const float* Wproj = (const float*)d_in[2];  // [1024,1024]
    float* out = (float*)d_out;                  // [4096,1024]

    float* qkv; cudaGetSymbolAddress((void**)&qkv, g_qkv);
    float* att; cudaGetSymbolAddress((void**)&att, g_att);

    cudaFuncSetAttribute(flash_attn_tc, cudaFuncAttributeMaxDynamicSharedMemorySize, FA_SMEM);

    // 1) qkv = x @ W_qkv^T
    dim3 g1((3 * D_DIM) / 128, T_DIM / 128);
    gemm_mma_tf32x3<<<g1, 256>>>(x, Wqkv, qkv, T_DIM, 3 * D_DIM, D_DIM);

    // 2) RoPE in place on q, k
    int total = T_DIM * H_NUM * (C_DIM / 2);
    rope_kernel<<<(total + 255) / 256, 256>>>(qkv);

    // 3) causal flash attention (tensor cores, pipelined) -> att [T][D]
    dim3 g2(T_DIM / 128, H_NUM);
    flash_attn_tc<<<g2, 256, FA_SMEM>>>(qkv, att);

    // 4) out = att @ W_proj^T
    dim3 g3(D_DIM / 128, T_DIM / 128);
    gemm_mma_tf32x3<<<g3, 256>>>(att, Wproj, out, T_DIM, D_DIM, D_DIM);
}